// round 5
// baseline (speedup 1.0000x reference)
#include <cuda_runtime.h>

#define NN   32
#define CIN  32
#define COUT 16
#define DD   16
#define WH   256
#define MM   8192   // CIN*WH
#define EPSF 1e-6f

// Scratch (device globals: allocation-free per harness rules)
__device__ float d_b[(size_t)NN * MM * COUT];      // 16 MB routing logits
__device__ float d_pmax[NN * COUT * CIN];          // per-(n,o,c) partial max
__device__ float d_psum[NN * COUT * CIN];          // per-(n,o,c) partial sumexp
__device__ float d_gmax[NN * COUT];                // global max per (n,o)
__device__ float d_ginv[NN * COUT];                // 1/sumexp per (n,o)
__device__ float d_T[NN * CIN * 16 * COUT];        // T[n][c][ij][o]
__device__ float d_g[NN * COUT * DD];              // current g

// ---------------------------------------------------------------------------
// b-pass: b[m,o] (+=) <L_m, H_{c,o}>, fused online softmax partial stats.
// grid (CIN, NN), 256 threads (one per s).
// ---------------------------------------------------------------------------
__global__ void k_bpass(const float* __restrict__ l,
                        const float* __restrict__ g0,
                        const float* __restrict__ wgt,
                        int is_update)
{
    const int c = blockIdx.x, n = blockIdx.y;
    const int tid = threadIdx.x;

    __shared__ float H[COUT][16];      // H[o][i*4+j]
    __shared__ float red[COUT][8];
    __shared__ float gmaxs[COUT];

    // Build H[o][i*4+j] = sum_k W[c,o,j,k] * g[n,o,i*4+k]   (one element/thread)
    {
        const int o = tid >> 4, i = (tid >> 2) & 3, j = tid & 3;
        const float* wp = wgt + ((size_t)(c * COUT + o) * 4 + j) * 4;
        const float* gp = (is_update ? d_g : g0) + (size_t)(n * COUT + o) * DD + i * 4;
        float h = 0.f;
        #pragma unroll
        for (int k = 0; k < 4; k++) h = fmaf(wp[k], gp[k], h);
        H[o][i * 4 + j] = h;
    }
    __syncthreads();

    // Load L[t] = l[n,c,d=t,s]
    float L[16];
    const float* lp = l + ((size_t)(n * CIN + c) * DD) * WH + tid;
    #pragma unroll
    for (int t = 0; t < 16; t++) L[t] = lp[t * WH];

    float b[16];
    float* brow = d_b + (size_t)(n * MM + c * WH + tid) * COUT;
    if (is_update) {
        #pragma unroll
        for (int o = 0; o < 16; o += 4) {
            float4 bv = *reinterpret_cast<const float4*>(brow + o);
            b[o] = bv.x; b[o+1] = bv.y; b[o+2] = bv.z; b[o+3] = bv.w;
        }
    } else {
        #pragma unroll
        for (int o = 0; o < 16; o++) b[o] = 0.f;
    }

    #pragma unroll
    for (int o = 0; o < 16; o++) {
        const float4* hp = reinterpret_cast<const float4*>(&H[o][0]);
        float4 h0 = hp[0], h1 = hp[1], h2 = hp[2], h3 = hp[3];
        float acc = b[o];
        acc = fmaf(L[0],  h0.x, acc); acc = fmaf(L[1],  h0.y, acc);
        acc = fmaf(L[2],  h0.z, acc); acc = fmaf(L[3],  h0.w, acc);
        acc = fmaf(L[4],  h1.x, acc); acc = fmaf(L[5],  h1.y, acc);
        acc = fmaf(L[6],  h1.z, acc); acc = fmaf(L[7],  h1.w, acc);
        acc = fmaf(L[8],  h2.x, acc); acc = fmaf(L[9],  h2.y, acc);
        acc = fmaf(L[10], h2.z, acc); acc = fmaf(L[11], h2.w, acc);
        acc = fmaf(L[12], h3.x, acc); acc = fmaf(L[13], h3.y, acc);
        acc = fmaf(L[14], h3.z, acc); acc = fmaf(L[15], h3.w, acc);
        b[o] = acc;
    }
    #pragma unroll
    for (int o = 0; o < 16; o += 4)
        *reinterpret_cast<float4*>(brow + o) = make_float4(b[o], b[o+1], b[o+2], b[o+3]);

    // Block-level softmax partials per o: max, then sum exp(b - max)
    const int lane = tid & 31, warp = tid >> 5;
    #pragma unroll
    for (int o = 0; o < 16; o++) {
        float v = b[o];
        #pragma unroll
        for (int off = 16; off; off >>= 1)
            v = fmaxf(v, __shfl_xor_sync(0xffffffffu, v, off));
        if (lane == 0) red[o][warp] = v;
    }
    __syncthreads();
    if (tid < 16) {
        float v = red[tid][0];
        #pragma unroll
        for (int w = 1; w < 8; w++) v = fmaxf(v, red[tid][w]);
        gmaxs[tid] = v;
    }
    __syncthreads();
    #pragma unroll
    for (int o = 0; o < 16; o++) {
        float e = __expf(b[o] - gmaxs[o]);
        #pragma unroll
        for (int off = 16; off; off >>= 1)
            e += __shfl_xor_sync(0xffffffffu, e, off);
        if (lane == 0) red[o][warp] = e;
    }
    __syncthreads();
    if (tid < 16) {
        float e = 0.f;
        #pragma unroll
        for (int w = 0; w < 8; w++) e += red[tid][w];
        d_pmax[(n * COUT + tid) * CIN + c] = gmaxs[tid];
        d_psum[(n * COUT + tid) * CIN + c] = e;
    }
}

// ---------------------------------------------------------------------------
// Finalize softmax stats: combine 32 c-partials per (n,o). grid NN, 512 thr.
// ---------------------------------------------------------------------------
__global__ void k_fin()
{
    const int n = blockIdx.x;
    const int o = threadIdx.x >> 5;
    const int c = threadIdx.x & 31;
    float pm = d_pmax[(n * COUT + o) * CIN + c];
    float ps = d_psum[(n * COUT + o) * CIN + c];
    float gm = pm;
    #pragma unroll
    for (int off = 16; off; off >>= 1)
        gm = fmaxf(gm, __shfl_xor_sync(0xffffffffu, gm, off));
    float e = ps * __expf(pm - gm);
    #pragma unroll
    for (int off = 16; off; off >>= 1)
        e += __shfl_xor_sync(0xffffffffu, e, off);
    if (c == 0) {
        d_gmax[n * COUT + o] = gm;
        d_ginv[n * COUT + o] = 1.0f / e;
    }
}

// ---------------------------------------------------------------------------
// s-pass: cc = softmax(b); T[n,c,ij,o] = sum_s cc[s,o]*L[s,ij].
// Optionally emit a = cc (final iteration). grid (CIN, NN), 256 threads.
// ---------------------------------------------------------------------------
__global__ void k_spass(const float* __restrict__ l,
                        float* __restrict__ a_out,
                        int write_a)
{
    const int c = blockIdx.x, n = blockIdx.y;
    const int tid = threadIdx.x;

    __shared__ float ccs[256][17];   // cc[s][o], pad 17 -> conflict-free
    __shared__ float Ls[256][17];    // L[s][ij]
    __shared__ float Tpart[4][256];  // chunk partials, [chunk][ij*16+o]
    __shared__ float smax[16], sinv[16];

    if (tid < 16) {
        smax[tid] = d_gmax[n * COUT + tid];
        sinv[tid] = d_ginv[n * COUT + tid];
    }

    const float* lp = l + ((size_t)(n * CIN + c) * DD) * WH + tid;
    #pragma unroll
    for (int t = 0; t < 16; t++) Ls[tid][t] = lp[t * WH];

    float b[16];
    const float* brow = d_b + (size_t)(n * MM + c * WH + tid) * COUT;
    #pragma unroll
    for (int o = 0; o < 16; o += 4) {
        float4 bv = *reinterpret_cast<const float4*>(brow + o);
        b[o] = bv.x; b[o+1] = bv.y; b[o+2] = bv.z; b[o+3] = bv.w;
    }
    __syncthreads();

    float cc[16];
    #pragma unroll
    for (int o = 0; o < 16; o++) {
        cc[o] = __expf(b[o] - smax[o]) * sinv[o];
        ccs[tid][o] = cc[o];
    }
    if (write_a) {
        float* ap = a_out + (size_t)(n * MM + c * WH + tid) * COUT;
        #pragma unroll
        for (int o = 0; o < 16; o += 4)
            *reinterpret_cast<float4*>(ap + o) =
                make_float4(cc[o], cc[o+1], cc[o+2], cc[o+3]);
    }
    __syncthreads();

    // Phase 2: 16x256x16 smem matmul. thread -> (o, ij-group, s-chunk)
    {
        const int o     = tid & 15;
        const int col   = ((tid >> 4) & 3) * 4;   // ij base
        const int chunk = tid >> 6;
        float a0 = 0.f, a1 = 0.f, a2 = 0.f, a3 = 0.f;
        const int s0 = chunk * 64;
        #pragma unroll 4
        for (int s = s0; s < s0 + 64; s++) {
            float w = ccs[s][o];
            a0 = fmaf(w, Ls[s][col + 0], a0);
            a1 = fmaf(w, Ls[s][col + 1], a1);
            a2 = fmaf(w, Ls[s][col + 2], a2);
            a3 = fmaf(w, Ls[s][col + 3], a3);
        }
        Tpart[chunk][(col + 0) * 16 + o] = a0;
        Tpart[chunk][(col + 1) * 16 + o] = a1;
        Tpart[chunk][(col + 2) * 16 + o] = a2;
        Tpart[chunk][(col + 3) * 16 + o] = a3;
    }
    __syncthreads();
    {
        float v = Tpart[0][tid] + Tpart[1][tid] + Tpart[2][tid] + Tpart[3][tid];
        d_T[((size_t)(n * CIN + c) * 16) * COUT + tid] = v;  // [ij][o], coalesced
    }
}

// ---------------------------------------------------------------------------
// squash: s[n,o,ik] = sum_c sum_j W[c,o,j,k]*T[n,c,i*4+j,o]; g = squash(s).
// grid NN, 256 threads (o*16 + ik).
// ---------------------------------------------------------------------------
__global__ void k_squash(const float* __restrict__ wgt,
                         float* __restrict__ g_out,
                         int write_g)
{
    const int n = blockIdx.x;
    const int tid = threadIdx.x;
    const int o = tid >> 4, ik = tid & 15;
    const int i = ik >> 2, k = ik & 3;

    float sv = 0.f;
    for (int c = 0; c < CIN; c++) {
        const float* tp = d_T + ((size_t)(n * CIN + c) * 16) * COUT;
        const float* wp = wgt + (size_t)((c * COUT + o) * 4) * 4;
        #pragma unroll
        for (int j = 0; j < 4; j++)
            sv = fmaf(wp[j * 4 + k], tp[(i * 4 + j) * COUT + o], sv);
    }
    float sq = sv * sv;
    #pragma unroll
    for (int off = 8; off; off >>= 1)
        sq += __shfl_xor_sync(0xffffffffu, sq, off);   // reduce within 16-lane group
    const float coef = sq / (1.f + sq) / (sqrtf(sq) + EPSF);
    const float gv = coef * sv;
    d_g[(n * COUT + o) * DD + ik] = gv;
    if (write_g) g_out[(n * COUT + o) * DD + ik] = gv;
}

// ---------------------------------------------------------------------------
extern "C" void kernel_launch(void* const* d_in, const int* in_sizes, int n_in,
                              void* d_out, int out_size)
{
    (void)in_sizes; (void)n_in; (void)out_size;
    const float* l = (const float*)d_in[0];
    const float* g = (const float*)d_in[1];
    const float* w = (const float*)d_in[2];
    float* out   = (float*)d_out;
    float* a_out = out;                              // [N, M, COUT]
    float* g_out = out + (size_t)NN * MM * COUT;     // [N, COUT, DD]

    dim3 grid(CIN, NN);
    k_bpass<<<grid, 256>>>(l, g, w, 0);
    k_fin<<<NN, 512>>>();
    for (int it = 0; it < 3; it++) {
        const int last = (it == 2);
        k_spass<<<grid, 256>>>(l, a_out, last);
        k_squash<<<NN, 256>>>(w, g_out, last);
        if (!last) {
            k_bpass<<<grid, 256>>>(l, g, w, 1);
            k_fin<<<NN, 512>>>();
        }
    }
}

// round 7
// speedup vs baseline: 1.0543x; 1.0543x over previous
#include <cuda_runtime.h>

#define NN   32
#define CIN  32
#define COUT 16
#define DD   16
#define WH   256
#define MM   8192   // CIN*WH
#define EPSF 1e-6f

// Scratch (device globals: allocation-free per harness rules)
__device__ float d_b[(size_t)NN * MM * COUT];      // 16 MB routing logits
__device__ float d_pmax[NN * COUT * CIN];          // per-(n,o,c) partial max
__device__ float d_psum[NN * COUT * CIN];          // per-(n,o,c) partial sumexp
__device__ float d_sc[(size_t)NN * CIN * 256];     // per-(n,c) contribution to s[o,ik]

// packed-f32x2 helpers
__device__ __forceinline__ unsigned long long pack2(float x) {
    unsigned long long p;
    asm("mov.b64 %0, {%1, %1};" : "=l"(p) : "r"(__float_as_uint(x)));
    return p;
}
__device__ __forceinline__ void fma2(unsigned long long& acc,
                                     unsigned long long a, unsigned long long b) {
    asm("fma.rn.f32x2 %0, %1, %2, %0;" : "+l"(acc) : "l"(a), "l"(b));
}
__device__ __forceinline__ void unpack2(unsigned long long v, float& lo, float& hi) {
    unsigned ulo, uhi;
    asm("mov.b64 {%0, %1}, %2;" : "=r"(ulo), "=r"(uhi) : "l"(v));
    lo = __uint_as_float(ulo); hi = __uint_as_float(uhi);
}

// ---------------------------------------------------------------------------
// b-pass: [update: g = squash(sum_c d_sc)]; H = W·g; b (+)= <L, H>;
// fused per-block softmax partial stats. grid (CIN, NN), 256 threads.
// ---------------------------------------------------------------------------
__global__ void k_bpass(const float* __restrict__ l,
                        const float* __restrict__ g0,
                        const float* __restrict__ wgt,
                        int is_update)
{
    const int c = blockIdx.x, n = blockIdx.y;
    const int tid = threadIdx.x;

    __shared__ __align__(16) float Hsm[256];   // Hsm[(i*4+j)*16 + o]
    __shared__ float gsm[256];                 // g[o*16 + ik]
    __shared__ float red[COUT][8];
    __shared__ float gmaxs[COUT];

    if (is_update) {
        // squash prologue: s[tid] = sum_c d_sc[n][c][tid], then squash per o
        float sv = 0.f;
        const float* sp = d_sc + (size_t)n * CIN * 256 + tid;
        #pragma unroll
        for (int c2 = 0; c2 < CIN; c2++) sv += sp[c2 * 256];
        float sq = sv * sv;
        #pragma unroll
        for (int off = 8; off; off >>= 1)
            sq += __shfl_xor_sync(0xffffffffu, sq, off);   // 16-lane group = one o
        const float coef = sq / (1.f + sq) / (sqrtf(sq) + EPSF);
        gsm[tid] = coef * sv;
        __syncthreads();
    }

    // Build Hsm[(i*4+j)*16+o] = sum_k W[c,o,j,k] * g[o, i*4+k]
    {
        const int o = tid >> 4, i = (tid >> 2) & 3, j = tid & 3;
        const float* wp = wgt + ((size_t)(c * COUT + o) * 4 + j) * 4;
        const float* gp = is_update ? (gsm + o * 16 + i * 4)
                                    : (g0 + (size_t)(n * COUT + o) * DD + i * 4);
        float h = 0.f;
        #pragma unroll
        for (int k = 0; k < 4; k++) h = fmaf(wp[k], gp[k], h);
        Hsm[(i * 4 + j) * 16 + o] = h;
    }
    __syncthreads();

    // Load L[t] = l[n,c,d=t,s=tid]; pack for f32x2
    float L[16];
    const float* lp = l + ((size_t)(n * CIN + c) * DD) * WH + tid;
    #pragma unroll
    for (int t = 0; t < 16; t++) L[t] = lp[t * WH];
    unsigned long long Lp[16];
    #pragma unroll
    for (int t = 0; t < 16; t++) Lp[t] = pack2(L[t]);

    float* brow = d_b + (size_t)(n * MM + c * WH + tid) * COUT;
    unsigned long long acc[8];
    if (is_update) {
        #pragma unroll
        for (int op = 0; op < 8; op++)
            acc[op] = *reinterpret_cast<const unsigned long long*>(brow + 2 * op);
    } else {
        #pragma unroll
        for (int op = 0; op < 8; op++) acc[op] = 0ull;   // (0.f, 0.f)
    }

    #pragma unroll
    for (int op = 0; op < 8; op++) {
        #pragma unroll
        for (int t = 0; t < 16; t++) {
            unsigned long long h2 =
                *reinterpret_cast<const unsigned long long*>(&Hsm[t * 16 + 2 * op]);
            fma2(acc[op], Lp[t], h2);
        }
    }

    float b[16];
    #pragma unroll
    for (int op = 0; op < 8; op++) {
        unpack2(acc[op], b[2 * op], b[2 * op + 1]);
        *reinterpret_cast<unsigned long long*>(brow + 2 * op) = acc[op];
    }

    // Block-level softmax partials per o: max, then sum exp(b - max)
    const int lane = tid & 31, warp = tid >> 5;
    #pragma unroll
    for (int o = 0; o < 16; o++) {
        float v = b[o];
        #pragma unroll
        for (int off = 16; off; off >>= 1)
            v = fmaxf(v, __shfl_xor_sync(0xffffffffu, v, off));
        if (lane == 0) red[o][warp] = v;
    }
    __syncthreads();
    if (tid < 16) {
        float v = red[tid][0];
        #pragma unroll
        for (int w = 1; w < 8; w++) v = fmaxf(v, red[tid][w]);
        gmaxs[tid] = v;
    }
    __syncthreads();
    #pragma unroll
    for (int o = 0; o < 16; o++) {
        float e = __expf(b[o] - gmaxs[o]);
        #pragma unroll
        for (int off = 16; off; off >>= 1)
            e += __shfl_xor_sync(0xffffffffu, e, off);
        if (lane == 0) red[o][warp] = e;
    }
    __syncthreads();
    if (tid < 16) {
        float e = 0.f;
        #pragma unroll
        for (int w = 0; w < 8; w++) e += red[tid][w];
        d_pmax[(n * COUT + tid) * CIN + c] = gmaxs[tid];
        d_psum[(n * COUT + tid) * CIN + c] = e;
    }
}

// ---------------------------------------------------------------------------
// s-pass: fin (global softmax stats from partials), cc = softmax(b),
// T[ij,o] = sum_s cc[s,o]*L[s,ij] in smem, then per-c contribution
// sc[o,ik] = sum_j W[c,o,j,k]*T[i4+j,o] -> d_sc. Optionally emit a = cc.
// grid (CIN, NN), 256 threads.
// ---------------------------------------------------------------------------
__global__ void k_spass(const float* __restrict__ l,
                        const float* __restrict__ wgt,
                        float* __restrict__ a_out,
                        int write_a)
{
    const int c = blockIdx.x, n = blockIdx.y;
    const int tid = threadIdx.x;

    __shared__ __align__(16) float ccs[256][18];   // cc[s][o]
    __shared__ __align__(16) float Ls[256][18];    // L[s][ij]
    __shared__ float Tpart[4][256];                // chunk partials / final T
    __shared__ float smax[16], sinv[16];

    // Fused finalize: combine 32 per-c softmax partials for this n
    {
        const int o = tid >> 4, ch = tid & 15;
        const float* pmp = d_pmax + (size_t)(n * COUT + o) * CIN + ch;
        const float* psp = d_psum + (size_t)(n * COUT + o) * CIN + ch;
        float m0 = pmp[0], m1 = pmp[16];
        float gm = fmaxf(m0, m1);
        #pragma unroll
        for (int off = 8; off; off >>= 1)
            gm = fmaxf(gm, __shfl_xor_sync(0xffffffffu, gm, off));
        float e = psp[0] * __expf(m0 - gm) + psp[16] * __expf(m1 - gm);
        #pragma unroll
        for (int off = 8; off; off >>= 1)
            e += __shfl_xor_sync(0xffffffffu, e, off);
        if (ch == 0) { smax[o] = gm; sinv[o] = 1.0f / e; }
    }

    const float* lp = l + ((size_t)(n * CIN + c) * DD) * WH + tid;
    #pragma unroll
    for (int t = 0; t < 16; t++) Ls[tid][t] = lp[t * WH];

    float b[16];
    const float* brow = d_b + (size_t)(n * MM + c * WH + tid) * COUT;
    #pragma unroll
    for (int o = 0; o < 16; o += 4) {
        float4 bv = *reinterpret_cast<const float4*>(brow + o);
        b[o] = bv.x; b[o+1] = bv.y; b[o+2] = bv.z; b[o+3] = bv.w;
    }
    __syncthreads();

    float cc[16];
    #pragma unroll
    for (int o = 0; o < 16; o++) {
        cc[o] = __expf(b[o] - smax[o]) * sinv[o];
        ccs[tid][o] = cc[o];
    }
    if (write_a) {
        float* ap = a_out + (size_t)(n * MM + c * WH + tid) * COUT;
        #pragma unroll
        for (int o = 0; o < 16; o += 4)
            *reinterpret_cast<float4*>(ap + o) =
                make_float4(cc[o], cc[o+1], cc[o+2], cc[o+3]);
    }
    __syncthreads();

    // Phase 2: 16x256x16 smem matmul with packed f32x2
    {
        const int o     = tid & 15;
        const int col   = ((tid >> 4) & 3) * 4;   // ij base
        const int chunk = tid >> 6;
        unsigned long long a01 = 0ull, a23 = 0ull;
        const int s0 = chunk * 64;
        #pragma unroll 4
        for (int s = s0; s < s0 + 64; s++) {
            unsigned long long wpk = pack2(ccs[s][o]);
            unsigned long long l01 =
                *reinterpret_cast<const unsigned long long*>(&Ls[s][col]);
            unsigned long long l23 =
                *reinterpret_cast<const unsigned long long*>(&Ls[s][col + 2]);
            fma2(a01, wpk, l01);
            fma2(a23, wpk, l23);
        }
        float a0, a1, a2, a3;
        unpack2(a01, a0, a1);
        unpack2(a23, a2, a3);
        Tpart[chunk][(col + 0) * 16 + o] = a0;
        Tpart[chunk][(col + 1) * 16 + o] = a1;
        Tpart[chunk][(col + 2) * 16 + o] = a2;
        Tpart[chunk][(col + 3) * 16 + o] = a3;
    }
    __syncthreads();
    {
        float v = Tpart[0][tid] + Tpart[1][tid] + Tpart[2][tid] + Tpart[3][tid];
        Tpart[0][tid] = v;   // Tsm[ij*16+o], own slot
    }
    __syncthreads();
    // Per-c contribution to s: sc[o,ik] = sum_j W[c,o,j,k] * T[i*4+j, o]
    {
        const float* Tsm = &Tpart[0][0];
        const int o = tid >> 4, ik = tid & 15, i = ik >> 2, k = ik & 3;
        const float* wp = wgt + (size_t)((c * COUT + o) * 4) * 4;
        float contrib = 0.f;
        #pragma unroll
        for (int j = 0; j < 4; j++)
            contrib = fmaf(wp[j * 4 + k], Tsm[(i * 4 + j) * 16 + o], contrib);
        d_sc[((size_t)n * CIN + c) * 256 + tid] = contrib;
    }
}

// ---------------------------------------------------------------------------
// Final g output: g = squash(sum_c d_sc). grid NN, 256 threads.
// ---------------------------------------------------------------------------
__global__ void k_gfinal(float* __restrict__ g_out)
{
    const int n = blockIdx.x;
    const int tid = threadIdx.x;
    float sv = 0.f;
    const float* sp = d_sc + (size_t)n * CIN * 256 + tid;
    #pragma unroll
    for (int c = 0; c < CIN; c++) sv += sp[c * 256];
    float sq = sv * sv;
    #pragma unroll
    for (int off = 8; off; off >>= 1)
        sq += __shfl_xor_sync(0xffffffffu, sq, off);
    const float coef = sq / (1.f + sq) / (sqrtf(sq) + EPSF);
    g_out[(size_t)n * 256 + tid] = coef * sv;
}

// ---------------------------------------------------------------------------
extern "C" void kernel_launch(void* const* d_in, const int* in_sizes, int n_in,
                              void* d_out, int out_size)
{
    (void)in_sizes; (void)n_in; (void)out_size;
    const float* l = (const float*)d_in[0];
    const float* g = (const float*)d_in[1];
    const float* w = (const float*)d_in[2];
    float* out   = (float*)d_out;
    float* a_out = out;                              // [N, M, COUT]
    float* g_out = out + (size_t)NN * MM * COUT;     // [N, COUT, DD]

    dim3 grid(CIN, NN);
    k_bpass<<<grid, 256>>>(l, g, w, 0);
    for (int it = 0; it < 3; it++) {
        const int last = (it == 2);
        k_spass<<<grid, 256>>>(l, w, a_out, last);
        if (!last) k_bpass<<<grid, 256>>>(l, g, w, 1);
    }
    k_gfinal<<<NN, 256>>>(g_out);
}

// round 8
// speedup vs baseline: 1.3123x; 1.2447x over previous
#include <cuda_runtime.h>

#define NN   32
#define CIN  32
#define COUT 16
#define DD   16
#define WH   256
#define MM   8192   // CIN*WH
#define EPSF 1e-6f

// Scratch (device globals: allocation-free per harness rules)
__device__ float d_Hc[NN * CIN * 256];             // cumulative H[n][c][ij][o] (1 MB)
__device__ float d_pmax[NN * COUT * CIN];          // per-(n,o,c) partial max
__device__ float d_psum[NN * COUT * CIN];          // per-(n,o,c) partial sumexp
__device__ float d_sc[(size_t)NN * CIN * 256];     // per-(n,c) contribution to s[o,ik]

typedef unsigned long long ull;

// packed-f32x2 helpers
__device__ __forceinline__ ull pack2(float x) {
    ull p;
    asm("mov.b64 %0, {%1, %1};" : "=l"(p) : "r"(__float_as_uint(x)));
    return p;
}
__device__ __forceinline__ ull packxy(float x, float y) {
    ull p;
    asm("mov.b64 %0, {%1, %2};" : "=l"(p)
        : "r"(__float_as_uint(x)), "r"(__float_as_uint(y)));
    return p;
}
__device__ __forceinline__ void fma2(ull& acc, ull a, ull b) {
    asm("fma.rn.f32x2 %0, %1, %2, %0;" : "+l"(acc) : "l"(a), "l"(b));
}
__device__ __forceinline__ void unpack2(ull v, float& lo, float& hi) {
    unsigned ulo, uhi;
    asm("mov.b64 {%0, %1}, %2;" : "=r"(ulo), "=r"(uhi) : "l"(v));
    lo = __uint_as_float(ulo); hi = __uint_as_float(uhi);
}

// b-evaluation: acc[p] (o=2p,2p+1) += L[t] * Hsm[t*16 + 2p..2p+1], all t
__device__ __forceinline__ void beval(const float* __restrict__ Hsm,
                                      const float* __restrict__ L, ull acc[8]) {
    const float4* Hv = reinterpret_cast<const float4*>(Hsm);
    #pragma unroll
    for (int t = 0; t < 16; t++) {
        float4 h0 = Hv[t * 4 + 0], h1 = Hv[t * 4 + 1];
        float4 h2 = Hv[t * 4 + 2], h3 = Hv[t * 4 + 3];
        ull Lt = pack2(L[t]);
        fma2(acc[0], Lt, packxy(h0.x, h0.y));
        fma2(acc[1], Lt, packxy(h0.z, h0.w));
        fma2(acc[2], Lt, packxy(h1.x, h1.y));
        fma2(acc[3], Lt, packxy(h1.z, h1.w));
        fma2(acc[4], Lt, packxy(h2.x, h2.y));
        fma2(acc[5], Lt, packxy(h2.z, h2.w));
        fma2(acc[6], Lt, packxy(h3.x, h3.y));
        fma2(acc[7], Lt, packxy(h3.z, h3.w));
    }
}

// ---------------------------------------------------------------------------
// b-pass: [update: g = squash(sum_c d_sc)]; H_t = W·g; Hcum (+)= H_t;
// b = <L, Hcum>; per-block softmax partial stats. grid (CIN, NN), 256 thr.
// ---------------------------------------------------------------------------
__global__ void k_bpass(const float* __restrict__ l,
                        const float* __restrict__ g0,
                        const float* __restrict__ wgt,
                        int is_update)
{
    const int c = blockIdx.x, n = blockIdx.y;
    const int tid = threadIdx.x;

    __shared__ __align__(16) float Hsm[256];   // Hcum[(i*4+j)*16 + o]
    __shared__ float gsm[256];                 // g[o*16 + ik]
    __shared__ float red[COUT][8];
    __shared__ float gmaxs[COUT];

    if (is_update) {
        // squash prologue: s[tid] = sum_c d_sc[n][c][tid], then squash per o
        float sv = 0.f;
        const float* sp = d_sc + (size_t)n * CIN * 256 + tid;
        #pragma unroll
        for (int c2 = 0; c2 < CIN; c2++) sv += sp[c2 * 256];
        float sq = sv * sv;
        #pragma unroll
        for (int off = 8; off; off >>= 1)
            sq += __shfl_xor_sync(0xffffffffu, sq, off);   // 16-lane group = one o
        const float coef = sq / (1.f + sq) / (sqrtf(sq) + EPSF);
        gsm[tid] = coef * sv;
        __syncthreads();
    }

    // H_t element: H[(i*4+j)*16+o] = sum_k W[c,o,j,k] * g[o, i*4+k]
    {
        const int o = tid >> 4, i = (tid >> 2) & 3, j = tid & 3;
        const float* wp = wgt + ((size_t)(c * COUT + o) * 4 + j) * 4;
        const float* gp = is_update ? (gsm + o * 16 + i * 4)
                                    : (g0 + (size_t)(n * COUT + o) * DD + i * 4);
        float h = 0.f;
        #pragma unroll
        for (int k = 0; k < 4; k++) h = fmaf(wp[k], gp[k], h);
        const int idx = (i * 4 + j) * 16 + o;
        float* hc = d_Hc + ((size_t)(n * CIN + c) * 256);
        if (is_update) h += hc[idx];
        hc[idx] = h;
        Hsm[idx] = h;
    }
    __syncthreads();

    // Load L[t] = l[n,c,d=t,s=tid]
    float L[16];
    const float* lp = l + ((size_t)(n * CIN + c) * DD) * WH + tid;
    #pragma unroll
    for (int t = 0; t < 16; t++) L[t] = lp[t * WH];

    ull acc[8];
    #pragma unroll
    for (int p = 0; p < 8; p++) acc[p] = 0ull;
    beval(Hsm, L, acc);

    float b[16];
    #pragma unroll
    for (int p = 0; p < 8; p++) unpack2(acc[p], b[2 * p], b[2 * p + 1]);

    // Block-level softmax partials per o: max, then sum exp(b - max)
    const int lane = tid & 31, warp = tid >> 5;
    #pragma unroll
    for (int o = 0; o < 16; o++) {
        float v = b[o];
        #pragma unroll
        for (int off = 16; off; off >>= 1)
            v = fmaxf(v, __shfl_xor_sync(0xffffffffu, v, off));
        if (lane == 0) red[o][warp] = v;
    }
    __syncthreads();
    if (tid < 16) {
        float v = red[tid][0];
        #pragma unroll
        for (int w = 1; w < 8; w++) v = fmaxf(v, red[tid][w]);
        gmaxs[tid] = v;
    }
    __syncthreads();
    #pragma unroll
    for (int o = 0; o < 16; o++) {
        float e = __expf(b[o] - gmaxs[o]);
        #pragma unroll
        for (int off = 16; off; off >>= 1)
            e += __shfl_xor_sync(0xffffffffu, e, off);
        if (lane == 0) red[o][warp] = e;
    }
    __syncthreads();
    if (tid < 16) {
        float e = 0.f;
        #pragma unroll
        for (int w = 0; w < 8; w++) e += red[tid][w];
        d_pmax[(n * COUT + tid) * CIN + c] = gmaxs[tid];
        d_psum[(n * COUT + tid) * CIN + c] = e;
    }
}

// ---------------------------------------------------------------------------
// s-pass: finalize softmax stats; b = <L, Hcum>; cc = softmax(b);
// T[ij,o] = sum_s cc[s,o]*L[s,ij]; sc[o,ik] = sum_j W[c,o,j,k]*T[i4+j,o].
// Optionally emit a = cc. grid (CIN, NN), 256 threads.
// ---------------------------------------------------------------------------
__global__ void k_spass(const float* __restrict__ l,
                        const float* __restrict__ wgt,
                        float* __restrict__ a_out,
                        int write_a)
{
    const int c = blockIdx.x, n = blockIdx.y;
    const int tid = threadIdx.x;

    __shared__ __align__(16) float Hsm[256];
    __shared__ __align__(16) float ccs[256][18];   // cc[s][o], 8B-aligned rows
    __shared__ __align__(16) float Ls[256][20];    // L[s][ij], 16B-aligned rows
    __shared__ float Tpart[8][256];                // per-warp chunk partials
    __shared__ float smax[16], sinv[16];

    Hsm[tid] = d_Hc[(size_t)(n * CIN + c) * 256 + tid];

    // Fused finalize: combine 32 per-c softmax partials for this n
    {
        const int o = tid >> 4, ch = tid & 15;
        const float* pmp = d_pmax + (size_t)(n * COUT + o) * CIN + ch;
        const float* psp = d_psum + (size_t)(n * COUT + o) * CIN + ch;
        float m0 = pmp[0], m1 = pmp[16];
        float gm = fmaxf(m0, m1);
        #pragma unroll
        for (int off = 8; off; off >>= 1)
            gm = fmaxf(gm, __shfl_xor_sync(0xffffffffu, gm, off));
        float e = psp[0] * __expf(m0 - gm) + psp[16] * __expf(m1 - gm);
        #pragma unroll
        for (int off = 8; off; off >>= 1)
            e += __shfl_xor_sync(0xffffffffu, e, off);
        if (ch == 0) { smax[o] = gm; sinv[o] = 1.0f / e; }
    }

    float L[16];
    const float* lp = l + ((size_t)(n * CIN + c) * DD) * WH + tid;
    #pragma unroll
    for (int t = 0; t < 16; t++) { L[t] = lp[t * WH]; Ls[tid][t] = L[t]; }
    __syncthreads();

    // Recompute b = <L, Hcum> (identical op order to k_bpass)
    ull acc[8];
    #pragma unroll
    for (int p = 0; p < 8; p++) acc[p] = 0ull;
    beval(Hsm, L, acc);
    float b[16];
    #pragma unroll
    for (int p = 0; p < 8; p++) unpack2(acc[p], b[2 * p], b[2 * p + 1]);

    float cc[16];
    #pragma unroll
    for (int o = 0; o < 16; o++) {
        cc[o] = __expf(b[o] - smax[o]) * sinv[o];
        ccs[tid][o] = cc[o];
    }
    if (write_a) {
        float* ap = a_out + (size_t)(n * MM + c * WH + tid) * COUT;
        #pragma unroll
        for (int o = 0; o < 16; o += 4)
            *reinterpret_cast<float4*>(ap + o) =
                make_float4(cc[o], cc[o+1], cc[o+2], cc[o+3]);
    }
    __syncthreads();

    // Phase 2: warp = one 32-s chunk (s uniform across warp -> broadcast LDS).
    // lane: p = lane&7 (o-pair 2p,2p+1), q = lane>>3 (cols 4q..4q+3).
    {
        const int w = tid >> 5, lane = tid & 31;
        const int p = lane & 7, q = lane >> 3;
        ull a2[4];
        #pragma unroll
        for (int e = 0; e < 4; e++) a2[e] = 0ull;
        const int s0 = w * 32;
        #pragma unroll 4
        for (int s = s0; s < s0 + 32; s++) {
            ull ccp = *reinterpret_cast<const ull*>(&ccs[s][2 * p]);
            float4 Lv = *reinterpret_cast<const float4*>(&Ls[s][4 * q]);
            fma2(a2[0], pack2(Lv.x), ccp);
            fma2(a2[1], pack2(Lv.y), ccp);
            fma2(a2[2], pack2(Lv.z), ccp);
            fma2(a2[3], pack2(Lv.w), ccp);
        }
        #pragma unroll
        for (int e = 0; e < 4; e++)
            *reinterpret_cast<ull*>(&Tpart[w][(4 * q + e) * 16 + 2 * p]) = a2[e];
    }
    __syncthreads();
    {
        float v = 0.f;
        #pragma unroll
        for (int w = 0; w < 8; w++) v += Tpart[w][tid];
        Tpart[0][tid] = v;   // Tsm[ij*16+o], own column only
    }
    __syncthreads();
    // Per-c contribution to s: sc[o,ik] = sum_j W[c,o,j,k] * T[i*4+j, o]
    {
        const float* Tsm = &Tpart[0][0];
        const int o = tid >> 4, ik = tid & 15, i = ik >> 2, k = ik & 3;
        const float* wp = wgt + (size_t)((c * COUT + o) * 4) * 4;
        float contrib = 0.f;
        #pragma unroll
        for (int j = 0; j < 4; j++)
            contrib = fmaf(wp[j * 4 + k], Tsm[(i * 4 + j) * 16 + o], contrib);
        d_sc[((size_t)n * CIN + c) * 256 + tid] = contrib;
    }
}

// ---------------------------------------------------------------------------
// Final g output: g = squash(sum_c d_sc). grid NN, 256 threads.
// ---------------------------------------------------------------------------
__global__ void k_gfinal(float* __restrict__ g_out)
{
    const int n = blockIdx.x;
    const int tid = threadIdx.x;
    float sv = 0.f;
    const float* sp = d_sc + (size_t)n * CIN * 256 + tid;
    #pragma unroll
    for (int c = 0; c < CIN; c++) sv += sp[c * 256];
    float sq = sv * sv;
    #pragma unroll
    for (int off = 8; off; off >>= 1)
        sq += __shfl_xor_sync(0xffffffffu, sq, off);
    const float coef = sq / (1.f + sq) / (sqrtf(sq) + EPSF);
    g_out[(size_t)n * 256 + tid] = coef * sv;
}

// ---------------------------------------------------------------------------
extern "C" void kernel_launch(void* const* d_in, const int* in_sizes, int n_in,
                              void* d_out, int out_size)
{
    (void)in_sizes; (void)n_in; (void)out_size;
    const float* l = (const float*)d_in[0];
    const float* g = (const float*)d_in[1];
    const float* w = (const float*)d_in[2];
    float* out   = (float*)d_out;
    float* a_out = out;                              // [N, M, COUT]
    float* g_out = out + (size_t)NN * MM * COUT;     // [N, COUT, DD]

    dim3 grid(CIN, NN);
    k_bpass<<<grid, 256>>>(l, g, w, 0);
    for (int it = 0; it < 3; it++) {
        const int last = (it == 2);
        k_spass<<<grid, 256>>>(l, w, a_out, last);
        if (!last) k_bpass<<<grid, 256>>>(l, g, w, 1);
    }
    k_gfinal<<<NN, 256>>>(g_out);
}